// round 14
// baseline (speedup 1.0000x reference)
#include <cuda_runtime.h>
#include <math.h>

#define NB 32
#define XD 521
#define TD 49
#define CW 64
#define VROW 3136                 // TD*CW
#define V_ELEMS  52283392ull      // NB*XD*VROW
#define PC_ELEMS 1605632ull      // NB*16*VROW (float2)
#define WT_ELEMS 4194304ull      // 4*256*64*64

typedef unsigned long long u64;

__device__ float g_v[V_ELEMS];
__device__ float g_u1[V_ELEMS];
__device__ float g_u1b[V_ELEMS];
__device__ float2 g_pc[PC_ELEMS];     // P partial (x-half 0)
__device__ float2 g_pc2[PC_ELEMS];    // P partial (x-half 1)
__device__ float2 g_rc[PC_ELEMS];     // R[b][kx][t*64+o]
__device__ float4 g_wtp[WT_ELEMS];    // (wr, wi, -wi, wr)  [l][m][c][o]
__device__ float2 g_exE[16 * 521];    // fwd x twiddle
__device__ float2 g_et1[784];         // [kt][t] fwd t
__device__ float2 g_et2[784];
__device__ float2 g_ct1[784];         // inv t (scaled)
__device__ float2 g_ct2[784];

__device__ __forceinline__ float gelu_f(float v) {
    return 0.5f * v * (1.0f + erff(v * 0.70710678118654752f));
}
__device__ __forceinline__ u64 pk(float lo, float hi) {
    u64 r; asm("mov.b64 %0,{%1,%2};" : "=l"(r) : "f"(lo), "f"(hi)); return r;
}
__device__ __forceinline__ u64 pk1(float v) { return pk(v, v); }
__device__ __forceinline__ void fma2(u64& d, u64 a, u64 b) {
    asm("fma.rn.f32x2 %0,%1,%2,%0;" : "+l"(d) : "l"(a), "l"(b));
}
__device__ __forceinline__ void add2(u64& d, u64 a) {
    asm("add.rn.f32x2 %0,%0,%1;" : "+l"(d) : "l"(a));
}
__device__ __forceinline__ float2 up2(u64 v) {
    float2 r; asm("mov.b64 {%0,%1},%2;" : "=f"(r.x), "=f"(r.y) : "l"(v)); return r;
}

// ---------- tables ----------
__global__ void k_tables() {
    int idx = blockIdx.x * blockDim.x + threadIdx.x;
    const double PI2 = 6.283185307179586476925287;
    if (idx < 784) {
        int kt = idx / 49, t = idx % 49;
        double a = -PI2 * (double)((kt * t) % 49) / 49.0;
        float er = (float)cos(a), ei = (float)sin(a);
        g_et1[idx] = make_float2(er, ei);
        g_et2[idx] = make_float2(-ei, er);
        float w = (kt == 0 ? 1.0f : 2.0f) * (float)(1.0 / (521.0 * 49.0));
        float ct = w * er;
        float cs = w * (-ei);
        g_ct1[idx] = make_float2(ct, cs);
        g_ct2[idx] = make_float2(-cs, ct);
    }
    if (idx < 8336) {
        int kx = idx / 521, x = idx % 521;
        double a = -PI2 * (double)((kx * x) % 521) / 521.0;
        g_exE[idx] = make_float2((float)cos(a), (float)sin(a));
    }
}

// ---------- spectral weight pack: (wr,wi,-wi,wr) float4 ----------
__global__ void k_wt2(const float* __restrict__ wr, const float* __restrict__ wi) {
    __shared__ float shr[64 * 65], shi[64 * 65];
    int mc = blockIdx.x, i = blockIdx.y, l = blockIdx.z, tid = threadIdx.x;
    size_t srcbase = ((size_t)(l * 64 + i)) * 64 * 256 + (size_t)mc * 64;
    for (int idx = tid; idx < 4096; idx += 256) {
        int o = idx >> 6, mm = idx & 63;
        shr[o * 65 + mm] = wr[srcbase + (size_t)o * 256 + mm];
        shi[o * 65 + mm] = wi[srcbase + (size_t)o * 256 + mm];
    }
    __syncthreads();
    for (int idx = tid; idx < 4096; idx += 256) {
        int mm = idx >> 6, o = idx & 63;
        int m = mc * 64 + mm;
        float r = shr[o * 65 + mm], im = shi[o * 65 + mm];
        size_t d = (((size_t)(l * 256 + m)) * 64 + i) * 64 + o;
        g_wtp[d] = make_float4(r, im, -im, r);
    }
}

// ---------- embed ----------
__global__ void __launch_bounds__(256) k_embed(const float* __restrict__ u,
                                               const float* __restrict__ xin,
                                               const float* __restrict__ tin,
                                               const float* __restrict__ par,
                                               const float* __restrict__ w0,
                                               const float* __restrict__ b0) {
    __shared__ float feat[4][16];
    __shared__ float tv[40];
    int xq = blockIdx.x, b = blockIdx.y, tid = threadIdx.x;
    int xh = tid >> 6, c = tid & 63;
    int x = xq * 4 + xh;
    if (tid < 40) tv[tid] = tin[b * 40 + tid];
    if (c < 13 && x < 512) {
        float f;
        if (c < 10) f = u[((size_t)(b * 512 + x)) * 10 + c];
        else if (c < 12) f = par[b * 2 + c - 10];
        else f = xin[b * 512 + x];
        feat[xh][c] = f;
    }
    __syncthreads();
    if (x >= XD) return;
    bool vx = (x < 512);
    size_t vb = ((size_t)(b * XD + x)) * VROW;
    float basev = 0.f, w13c = 0.f;
    if (vx) {
        basev = b0[c];
#pragma unroll
        for (int k = 0; k < 13; k++) basev += feat[xh][k] * w0[k * 64 + c];
        w13c = w0[13 * 64 + c];
    }
    for (int t = 0; t < 40; t++)
        g_v[vb + t * 64 + c] = vx ? fmaf(tv[t], w13c, basev) : 0.f;
    for (int t = 40; t < 49; t++) g_v[vb + t * 64 + c] = 0.f;
}

// ---------- forward x-DFT: 2 cols/thread, 8 kx (paired twiddles), 2 x-halves ----------
__global__ void __launch_bounds__(224) k_fx() {
    __shared__ __align__(16) float4 exs4[4 * 132];
    int jt = blockIdx.x;            // 0..6 col tile
    int q = blockIdx.y;             // 0..3 : kxh = q&1, xhf = q>>1
    int b = blockIdx.z;
    int tid = threadIdx.x;
    int kxh = (q & 1) * 8, xhf = q >> 1;
    int col0 = (jt * 224 + tid) * 2;
    int xbeg = xhf * 261, xend = xhf ? 521 : 261;
    size_t vb = (size_t)b * XD * VROW;
    u64 a0[8], a1[8];
#pragma unroll
    for (int kx = 0; kx < 8; kx++) { a0[kx] = 0ull; a1[kx] = 0ull; }
    for (int ch = 0; ch < 2; ch++) {
        int x0 = xbeg + ch * 131;
        int cnt = min(131, xend - x0);
        __syncthreads();
        for (int i = tid; i < 4 * cnt; i += 224) {
            int kp = i / cnt, xl = i - kp * cnt;
            float2 e0 = g_exE[(kxh + kp * 2) * 521 + x0 + xl];
            float2 e1 = g_exE[(kxh + kp * 2 + 1) * 521 + x0 + xl];
            exs4[kp * 132 + xl] = make_float4(e0.x, e0.y, e1.x, e1.y);
        }
        __syncthreads();
        for (int xl = 0; xl < cnt; xl++) {
            u64 v2 = *(const u64*)(g_v + vb + (size_t)(x0 + xl) * VROW + col0);
            float2 vv = up2(v2);
            u64 va = pk1(vv.x), vc = pk1(vv.y);
#pragma unroll
            for (int kp = 0; kp < 4; kp++) {
                float4 e = exs4[kp * 132 + xl];
                u64 E0 = *(u64*)&e.x, E1 = *(u64*)&e.z;
                fma2(a0[kp * 2], va, E0); fma2(a1[kp * 2], vc, E0);
                fma2(a0[kp * 2 + 1], va, E1); fma2(a1[kp * 2 + 1], vc, E1);
            }
        }
    }
    float2* dst = xhf ? g_pc2 : g_pc;
#pragma unroll
    for (int kx = 0; kx < 8; kx++) {
        ulonglong2 st;
        st.x = a0[kx]; st.y = a1[kx];
        *(ulonglong2*)(&dst[((size_t)(b * 16 + kxh + kx)) * VROW + col0]) = st;
    }
}

// ---------- spectral: t-DFT + channel mix + inv t-DFT per (kx, b), smem twiddles ----------
__global__ void __launch_bounds__(256) k_spec(int l) {
    // region A: [0, 25088)  Ps -> after phase1: cts4 (12544) @0, Ss (8192) @12544
    // region B: [25088, 37632) ets4
    // region C: [37632, 45824) Qs
    __shared__ __align__(16) char sm[45824];
    float2* Ps   = (float2*)sm;
    float4* ets4 = (float4*)(sm + 25088);
    float2* Qs   = (float2*)(sm + 37632);
    float4* cts4 = (float4*)sm;
    float2* Ss   = (float2*)(sm + 12544);
    int kx = blockIdx.x, b = blockIdx.y, tid = threadIdx.x;
    size_t base = ((size_t)(b * 16 + kx)) * VROW;
    for (int i = tid; i < VROW; i += 256) {
        float2 p0 = g_pc[base + i], p1 = g_pc2[base + i];
        Ps[i] = make_float2(p0.x + p1.x, p0.y + p1.y);
    }
    for (int i = tid; i < 784; i += 256) {
        float2 e1 = g_et1[i], e2 = g_et2[i];
        ets4[i] = make_float4(e1.x, e1.y, e2.x, e2.y);
    }
    __syncthreads();
    // phase1: t-DFT. thread owns (c, 4 kt)
    {
        int c = tid & 63, ktg = tid >> 6;
        u64 Q[4];
#pragma unroll
        for (int j = 0; j < 4; j++) Q[j] = 0ull;
        for (int t = 0; t < 49; t++) {
            float2 Pf = Ps[t * 64 + c];
            u64 px = pk1(Pf.x), py = pk1(Pf.y);
#pragma unroll
            for (int j = 0; j < 4; j++) {
                int kt = ktg * 4 + j;
                float4 e = ets4[kt * 49 + t];
                fma2(Q[j], px, *(u64*)&e.x);
                fma2(Q[j], py, *(u64*)&e.z);
            }
        }
#pragma unroll
        for (int j = 0; j < 4; j++)
            Qs[(ktg * 4 + j) * 64 + c] = up2(Q[j]);
    }
    __syncthreads();   // Ps dead, Qs visible
    for (int i = tid; i < 784; i += 256) {
        float2 c1 = g_ct1[i], c2 = g_ct2[i];
        cts4[i] = make_float4(c1.x, c1.y, c2.x, c2.y);
    }
    // phase2: mix, packed weights (1 LDG.128 per c)
    for (int i = tid; i < 1024; i += 256) {
        int kt = i >> 6, o = i & 63;
        u64 S = 0ull;
        size_t wb = ((size_t)(l * 256 + kx * 16 + kt)) * 4096 + o;
        for (int c = 0; c < 64; c++) {
            float2 q = Qs[kt * 64 + c];
            float4 w = g_wtp[wb + c * 64];
            fma2(S, pk1(q.x), *(u64*)&w.x);
            fma2(S, pk1(q.y), *(u64*)&w.z);
        }
        Ss[i] = up2(S);
    }
    __syncthreads();
    // phase3: inv t-DFT, kt outer, R in regs
    {
        int o = tid & 63, tg = tid >> 6;
        u64 R[13];
#pragma unroll
        for (int it = 0; it < 13; it++) R[it] = 0ull;
#pragma unroll 4
        for (int kt = 0; kt < 16; kt++) {
            float2 s = Ss[kt * 64 + o];
            u64 px = pk1(s.x), py = pk1(s.y);
#pragma unroll
            for (int it = 0; it < 13; it++) {
                int t = tg + it * 4;
                if (t < 49) {
                    float4 ct = cts4[kt * 49 + t];
                    fma2(R[it], px, *(u64*)&ct.x);
                    fma2(R[it], py, *(u64*)&ct.z);
                }
            }
        }
#pragma unroll
        for (int it = 0; it < 13; it++) {
            int t = tg + it * 4;
            if (t < 49) g_rc[base + t * 64 + o] = up2(R[it]);
        }
    }
}

// ---------- inverse x-DFT: 2 cols/thread, kx-half split, paired twiddles ----------
__global__ void __launch_bounds__(224) k_ix() {
    __shared__ __align__(16) float4 exs4[4 * 176];
    int jt = blockIdx.x;            // 0..6
    int yz = blockIdx.y;            // 0..5 : xc = yz>>1, kxh = (yz&1)*8
    int b = blockIdx.z;
    int tid = threadIdx.x;
    int xc = yz >> 1, kxh = (yz & 1) * 8;
    int col0 = (jt * 224 + tid) * 2;
    int x0 = xc * 174;
    int cnt = min(174, XD - x0);
    ulonglong2 Rv[8];
#pragma unroll
    for (int kx = 0; kx < 8; kx++)
        Rv[kx] = *(const ulonglong2*)(&g_rc[((size_t)(b * 16 + kxh + kx)) * VROW + col0]);
    for (int i = tid; i < 4 * cnt; i += 224) {
        int kp = i / cnt, xl = i - kp * cnt;
        float2 e0 = g_exE[(kxh + kp * 2) * 521 + x0 + xl];
        float2 e1 = g_exE[(kxh + kp * 2 + 1) * 521 + x0 + xl];
        exs4[kp * 176 + xl] = make_float4(e0.x, e0.y, e1.x, e1.y);
    }
    __syncthreads();
    float* dst = kxh ? g_u1b : g_u1;
    for (int xl = 0; xl < cnt; xl++) {
        u64 d0 = 0ull, d1 = 0ull;
#pragma unroll
        for (int kp = 0; kp < 4; kp++) {
            float4 e = exs4[kp * 176 + xl];
            u64 E0 = *(u64*)&e.x, E1 = *(u64*)&e.z;
            fma2(d0, Rv[kp * 2].x, E0);
            fma2(d1, Rv[kp * 2].y, E0);
            fma2(d0, Rv[kp * 2 + 1].x, E1);
            fma2(d1, Rv[kp * 2 + 1].y, E1);
        }
        float2 f0 = up2(d0), f1 = up2(d1);
        *(u64*)(dst + (size_t)(b * XD + x0 + xl) * VROW + col0) = pk(f0.x + f0.y, f1.x + f1.y);
    }
}

// ---------- conv (64x64) + bias + u1a+u1b + gelu, in-place ----------
__global__ void __launch_bounds__(128) k_conv(const float* __restrict__ wconv,
                                              const float* __restrict__ wbias,
                                              int l, int last) {
    __shared__ __align__(16) float v_sh[3328];
    __shared__ __align__(16) float wT[4096];
    __shared__ __align__(16) float bsh[64];
    int x = blockIdx.x, b = blockIdx.y, tid = threadIdx.x;
    size_t vb = ((size_t)(b * XD + x)) * VROW;
    for (int i = tid; i < 784; i += 128) ((float4*)v_sh)[i] = ((const float4*)(g_v + vb))[i];
    for (int i = 3136 + tid; i < 3328; i += 128) v_sh[i] = 0.f;
    for (int i = tid; i < 4096; i += 128) {
        int o = i >> 6, c = i & 63;
        wT[c * 64 + o] = wconv[l * 4096 + i];
    }
    if (tid < 64) bsh[tid] = wbias[l * 64 + tid];
    __syncthreads();

    int og = tid & 7, tg = tid >> 3;
    int t0 = tg * 4;
    if (t0 >= 49) return;
    u64 A[4][4];
    {
        const ulonglong2* bp = (const ulonglong2*)bsh;
        ulonglong2 B0 = bp[og * 2], B1 = bp[og * 2 + 1];
#pragma unroll
        for (int tt = 0; tt < 4; tt++) {
            A[tt][0] = B0.x; A[tt][1] = B0.y; A[tt][2] = B1.x; A[tt][3] = B1.y;
        }
    }
    const float4* v4p = (const float4*)v_sh;
    const ulonglong2* wp2 = (const ulonglong2*)wT;
#pragma unroll 4
    for (int cq = 0; cq < 16; cq++) {
        float4 v0 = v4p[(t0 + 0) * 16 + cq];
        float4 v1 = v4p[(t0 + 1) * 16 + cq];
        float4 v2 = v4p[(t0 + 2) * 16 + cq];
        float4 v3 = v4p[(t0 + 3) * 16 + cq];
#pragma unroll
        for (int cc = 0; cc < 4; cc++) {
            int c = cq * 4 + cc;
            ulonglong2 W0 = wp2[c * 16 + og * 2];
            ulonglong2 W1 = wp2[c * 16 + og * 2 + 1];
            float s0 = (cc == 0) ? v0.x : (cc == 1) ? v0.y : (cc == 2) ? v0.z : v0.w;
            float s1 = (cc == 0) ? v1.x : (cc == 1) ? v1.y : (cc == 2) ? v1.z : v1.w;
            float s2 = (cc == 0) ? v2.x : (cc == 1) ? v2.y : (cc == 2) ? v2.z : v2.w;
            float s3 = (cc == 0) ? v3.x : (cc == 1) ? v3.y : (cc == 2) ? v3.z : v3.w;
            u64 p0 = pk1(s0), p1 = pk1(s1), p2 = pk1(s2), p3 = pk1(s3);
            fma2(A[0][0], W0.x, p0); fma2(A[0][1], W0.y, p0); fma2(A[0][2], W1.x, p0); fma2(A[0][3], W1.y, p0);
            fma2(A[1][0], W0.x, p1); fma2(A[1][1], W0.y, p1); fma2(A[1][2], W1.x, p1); fma2(A[1][3], W1.y, p1);
            fma2(A[2][0], W0.x, p2); fma2(A[2][1], W0.y, p2); fma2(A[2][2], W1.x, p2); fma2(A[2][3], W1.y, p2);
            fma2(A[3][0], W0.x, p3); fma2(A[3][1], W0.y, p3); fma2(A[3][2], W1.x, p3); fma2(A[3][3], W1.y, p3);
        }
    }
#pragma unroll
    for (int tt = 0; tt < 4; tt++) {
        int t = t0 + tt;
        if (t < 49) {
            size_t bu = vb + t * 64 + og * 8;
            ulonglong2 U0 = *(const ulonglong2*)(g_u1 + bu);
            ulonglong2 U1 = *(const ulonglong2*)(g_u1 + bu + 4);
            ulonglong2 V0 = *(const ulonglong2*)(g_u1b + bu);
            ulonglong2 V1 = *(const ulonglong2*)(g_u1b + bu + 4);
            add2(A[tt][0], U0.x); add2(A[tt][1], U0.y);
            add2(A[tt][2], U1.x); add2(A[tt][3], U1.y);
            add2(A[tt][0], V0.x); add2(A[tt][1], V0.y);
            add2(A[tt][2], V1.x); add2(A[tt][3], V1.y);
            float2 r0 = up2(A[tt][0]), r1 = up2(A[tt][1]);
            float2 r2 = up2(A[tt][2]), r3 = up2(A[tt][3]);
            float4 fa, fb;
            if (!last) {
                fa = make_float4(gelu_f(r0.x), gelu_f(r0.y), gelu_f(r1.x), gelu_f(r1.y));
                fb = make_float4(gelu_f(r2.x), gelu_f(r2.y), gelu_f(r3.x), gelu_f(r3.y));
            } else {
                fa = make_float4(r0.x, r0.y, r1.x, r1.y);
                fb = make_float4(r2.x, r2.y, r3.x, r3.y);
            }
            ((float4*)(g_v + vb))[t * 16 + og * 2] = fa;
            ((float4*)(g_v + vb))[t * 16 + og * 2 + 1] = fb;
        }
    }
}

// ---------- crop + fc1 + gelu + fc2 ----------
__global__ void __launch_bounds__(256) k_final(const float* __restrict__ w1,
                                               const float* __restrict__ b1,
                                               const float* __restrict__ w2,
                                               const float* __restrict__ b2,
                                               float* __restrict__ out) {
    __shared__ __align__(16) float w1s[64 * 128];
    __shared__ __align__(16) float vs[40 * 64];
    __shared__ __align__(16) float b1s[128], w2s[128];
    __shared__ float b2s;
    int x = blockIdx.x, b = blockIdx.y, tid = threadIdx.x;
    for (int i = tid; i < 8192; i += 256) w1s[i] = w1[i];
    if (tid < 128) { b1s[tid] = b1[tid]; w2s[tid] = w2[tid]; }
    if (tid == 0) b2s = b2[0];
    size_t vb = ((size_t)(b * XD + x)) * VROW;
    for (int i = tid; i < 640; i += 256) ((float4*)vs)[i] = ((const float4*)(g_v + vb))[i];
    __syncthreads();
    int lane = tid & 31, wp = tid >> 5;
    u64 H[5][2];
    ulonglong2 bq = ((const ulonglong2*)b1s)[lane];
#pragma unroll
    for (int s = 0; s < 5; s++) { H[s][0] = bq.x; H[s][1] = bq.y; }
    const ulonglong2* w1p = (const ulonglong2*)w1s;
#pragma unroll 4
    for (int c = 0; c < 64; c++) {
        ulonglong2 w2v = w1p[c * 32 + lane];
#pragma unroll
        for (int s = 0; s < 5; s++) {
            u64 vv = pk1(vs[(wp + 8 * s) * 64 + c]);
            fma2(H[s][0], w2v.x, vv);
            fma2(H[s][1], w2v.y, vv);
        }
    }
    float4 w2q = ((const float4*)w2s)[lane];
#pragma unroll
    for (int s = 0; s < 5; s++) {
        float2 hlo = up2(H[s][0]), hhi = up2(H[s][1]);
        float acc = gelu_f(hlo.x) * w2q.x + gelu_f(hlo.y) * w2q.y +
                    gelu_f(hhi.x) * w2q.z + gelu_f(hhi.y) * w2q.w;
#pragma unroll
        for (int off = 16; off; off >>= 1) acc += __shfl_xor_sync(0xffffffffu, acc, off);
        if (lane == 0) out[((size_t)(b * 512 + x)) * 40 + wp + 8 * s] = acc + b2s;
    }
}

extern "C" void kernel_launch(void* const* d_in, const int* in_sizes, int n_in,
                              void* d_out, int out_size) {
    (void)in_sizes; (void)n_in; (void)out_size;
    const float* u      = (const float*)d_in[0];
    const float* xin    = (const float*)d_in[1];
    const float* tin    = (const float*)d_in[2];
    const float* par    = (const float*)d_in[3];
    const float* fc0_w  = (const float*)d_in[4];
    const float* fc0_b  = (const float*)d_in[5];
    const float* spec_wr = (const float*)d_in[6];
    const float* spec_wi = (const float*)d_in[7];
    const float* w_conv = (const float*)d_in[8];
    const float* w_bias = (const float*)d_in[9];
    const float* fc1_w  = (const float*)d_in[10];
    const float* fc1_b  = (const float*)d_in[11];
    const float* fc2_w  = (const float*)d_in[12];
    const float* fc2_b  = (const float*)d_in[13];
    float* out = (float*)d_out;

    k_tables<<<33, 256>>>();
    k_wt2<<<dim3(4, 64, 4), 256>>>(spec_wr, spec_wi);
    k_embed<<<dim3(131, NB), 256>>>(u, xin, tin, par, fc0_w, fc0_b);
    for (int l = 0; l < 4; l++) {
        k_fx<<<dim3(7, 4, NB), 224>>>();
        k_spec<<<dim3(16, NB), 256>>>(l);
        k_ix<<<dim3(7, 6, NB), 224>>>();
        k_conv<<<dim3(XD, NB), 128>>>(w_conv, w_bias, l, l == 3 ? 1 : 0);
    }
    k_final<<<dim3(512, NB), 256>>>(fc1_w, fc1_b, fc2_w, fc2_b, out);
}

// round 15
// speedup vs baseline: 1.0631x; 1.0631x over previous
#include <cuda_runtime.h>
#include <math.h>

#define NB 32
#define XD 521
#define TD 49
#define CW 64
#define VROW 3136                 // TD*CW
#define V_ELEMS  52283392ull      // NB*XD*VROW
#define PC_ELEMS 1605632ull      // NB*16*VROW (float2)
#define WT_ELEMS 4194304ull      // 4*256*64*64

typedef unsigned long long u64;

__device__ float g_v[V_ELEMS];
__device__ float g_u1[V_ELEMS];
__device__ float g_u1b[V_ELEMS];
__device__ float2 g_pc[PC_ELEMS];     // P partial (x-half 0)
__device__ float2 g_pc2[PC_ELEMS];    // P partial (x-half 1)
__device__ float2 g_rc[PC_ELEMS];     // R[b][kx][t*64+o]
__device__ float4 g_wtp[WT_ELEMS];    // (wr, wi, -wi, wr)  [l][m][c][o]
__device__ float2 g_exE[16 * 521];    // fwd x twiddle
__device__ float2 g_et1[784];         // [kt][t] fwd t
__device__ float2 g_et2[784];
__device__ float2 g_ct1[784];         // inv t (scaled)
__device__ float2 g_ct2[784];

__device__ __forceinline__ float gelu_f(float v) {
    return 0.5f * v * (1.0f + erff(v * 0.70710678118654752f));
}
__device__ __forceinline__ u64 pk(float lo, float hi) {
    u64 r; asm("mov.b64 %0,{%1,%2};" : "=l"(r) : "f"(lo), "f"(hi)); return r;
}
__device__ __forceinline__ u64 pk1(float v) { return pk(v, v); }
__device__ __forceinline__ void fma2(u64& d, u64 a, u64 b) {
    asm("fma.rn.f32x2 %0,%1,%2,%0;" : "+l"(d) : "l"(a), "l"(b));
}
__device__ __forceinline__ void add2(u64& d, u64 a) {
    asm("add.rn.f32x2 %0,%0,%1;" : "+l"(d) : "l"(a));
}
__device__ __forceinline__ float2 up2(u64 v) {
    float2 r; asm("mov.b64 {%0,%1},%2;" : "=f"(r.x), "=f"(r.y) : "l"(v)); return r;
}

// ---------- tables ----------
__global__ void k_tables() {
    int idx = blockIdx.x * blockDim.x + threadIdx.x;
    const double PI2 = 6.283185307179586476925287;
    if (idx < 784) {
        int kt = idx / 49, t = idx % 49;
        double a = -PI2 * (double)((kt * t) % 49) / 49.0;
        float er = (float)cos(a), ei = (float)sin(a);
        g_et1[idx] = make_float2(er, ei);
        g_et2[idx] = make_float2(-ei, er);
        float w = (kt == 0 ? 1.0f : 2.0f) * (float)(1.0 / (521.0 * 49.0));
        float ct = w * er;
        float cs = w * (-ei);
        g_ct1[idx] = make_float2(ct, cs);
        g_ct2[idx] = make_float2(-cs, ct);
    }
    if (idx < 8336) {
        int kx = idx / 521, x = idx % 521;
        double a = -PI2 * (double)((kx * x) % 521) / 521.0;
        g_exE[idx] = make_float2((float)cos(a), (float)sin(a));
    }
}

// ---------- spectral weight pack: (wr,wi,-wi,wr) float4 ----------
__global__ void k_wt2(const float* __restrict__ wr, const float* __restrict__ wi) {
    __shared__ float shr[64 * 65], shi[64 * 65];
    int mc = blockIdx.x, i = blockIdx.y, l = blockIdx.z, tid = threadIdx.x;
    size_t srcbase = ((size_t)(l * 64 + i)) * 64 * 256 + (size_t)mc * 64;
    for (int idx = tid; idx < 4096; idx += 256) {
        int o = idx >> 6, mm = idx & 63;
        shr[o * 65 + mm] = wr[srcbase + (size_t)o * 256 + mm];
        shi[o * 65 + mm] = wi[srcbase + (size_t)o * 256 + mm];
    }
    __syncthreads();
    for (int idx = tid; idx < 4096; idx += 256) {
        int mm = idx >> 6, o = idx & 63;
        int m = mc * 64 + mm;
        float r = shr[o * 65 + mm], im = shi[o * 65 + mm];
        size_t d = (((size_t)(l * 256 + m)) * 64 + i) * 64 + o;
        g_wtp[d] = make_float4(r, im, -im, r);
    }
}

// ---------- embed ----------
__global__ void __launch_bounds__(256) k_embed(const float* __restrict__ u,
                                               const float* __restrict__ xin,
                                               const float* __restrict__ tin,
                                               const float* __restrict__ par,
                                               const float* __restrict__ w0,
                                               const float* __restrict__ b0) {
    __shared__ float feat[4][16];
    __shared__ float tv[40];
    int xq = blockIdx.x, b = blockIdx.y, tid = threadIdx.x;
    int xh = tid >> 6, c = tid & 63;
    int x = xq * 4 + xh;
    if (tid < 40) tv[tid] = tin[b * 40 + tid];
    if (c < 13 && x < 512) {
        float f;
        if (c < 10) f = u[((size_t)(b * 512 + x)) * 10 + c];
        else if (c < 12) f = par[b * 2 + c - 10];
        else f = xin[b * 512 + x];
        feat[xh][c] = f;
    }
    __syncthreads();
    if (x >= XD) return;
    bool vx = (x < 512);
    size_t vb = ((size_t)(b * XD + x)) * VROW;
    float basev = 0.f, w13c = 0.f;
    if (vx) {
        basev = b0[c];
#pragma unroll
        for (int k = 0; k < 13; k++) basev += feat[xh][k] * w0[k * 64 + c];
        w13c = w0[13 * 64 + c];
    }
    for (int t = 0; t < 40; t++)
        g_v[vb + t * 64 + c] = vx ? fmaf(tv[t], w13c, basev) : 0.f;
    for (int t = 40; t < 49; t++) g_v[vb + t * 64 + c] = 0.f;
}

// ---------- forward x-DFT: 2 cols/thread, 8 kx, 2 x-halves (R13 proven) ----------
__global__ void __launch_bounds__(224) k_fx() {
    __shared__ float2 exs[8 * 132];
    int jt = blockIdx.x;            // 0..6 col tile
    int q = blockIdx.y;             // 0..3 : kxh = q&1, xhf = q>>1
    int b = blockIdx.z;
    int tid = threadIdx.x;
    int kxh = (q & 1) * 8, xhf = q >> 1;
    int col0 = (jt * 224 + tid) * 2;
    int xbeg = xhf * 261, xend = xhf ? 521 : 261;
    size_t vb = (size_t)b * XD * VROW;
    u64 a0[8], a1[8];
#pragma unroll
    for (int kx = 0; kx < 8; kx++) { a0[kx] = 0ull; a1[kx] = 0ull; }
    for (int ch = 0; ch < 2; ch++) {
        int x0 = xbeg + ch * 131;
        int cnt = min(131, xend - x0);
        __syncthreads();
        for (int i = tid; i < 8 * cnt; i += 224) {
            int kx = i / cnt, xl = i - kx * cnt;
            exs[kx * 132 + xl] = g_exE[(kxh + kx) * 521 + x0 + xl];
        }
        __syncthreads();
        for (int xl = 0; xl < cnt; xl++) {
            u64 v2 = *(const u64*)(g_v + vb + (size_t)(x0 + xl) * VROW + col0);
            float2 vv = up2(v2);
            u64 va = pk1(vv.x), vc = pk1(vv.y);
#pragma unroll
            for (int kx = 0; kx < 8; kx++) {
                u64 E = *(const u64*)&exs[kx * 132 + xl];
                fma2(a0[kx], va, E);
                fma2(a1[kx], vc, E);
            }
        }
    }
    float2* dst = xhf ? g_pc2 : g_pc;
#pragma unroll
    for (int kx = 0; kx < 8; kx++) {
        ulonglong2 st;
        st.x = a0[kx]; st.y = a1[kx];
        *(ulonglong2*)(&dst[((size_t)(b * 16 + kxh + kx)) * VROW + col0]) = st;
    }
}

// ---------- spectral: t-DFT + channel mix + inv t-DFT per (kx, b), smem twiddles ----------
__global__ void __launch_bounds__(256) k_spec(int l) {
    // region A: [0, 25088)  Ps -> after phase1: cts4 (12544) @0, Ss (8192) @12544
    // region B: [25088, 37632) ets4
    // region C: [37632, 45824) Qs
    __shared__ __align__(16) char sm[45824];
    float2* Ps   = (float2*)sm;
    float4* ets4 = (float4*)(sm + 25088);
    float2* Qs   = (float2*)(sm + 37632);
    float4* cts4 = (float4*)sm;
    float2* Ss   = (float2*)(sm + 12544);
    int kx = blockIdx.x, b = blockIdx.y, tid = threadIdx.x;
    size_t base = ((size_t)(b * 16 + kx)) * VROW;
    for (int i = tid; i < VROW; i += 256) {
        float2 p0 = g_pc[base + i], p1 = g_pc2[base + i];
        Ps[i] = make_float2(p0.x + p1.x, p0.y + p1.y);
    }
    for (int i = tid; i < 784; i += 256) {
        float2 e1 = g_et1[i], e2 = g_et2[i];
        ets4[i] = make_float4(e1.x, e1.y, e2.x, e2.y);
    }
    __syncthreads();
    // phase1: t-DFT. thread owns (c, 4 kt)
    {
        int c = tid & 63, ktg = tid >> 6;
        u64 Q[4];
#pragma unroll
        for (int j = 0; j < 4; j++) Q[j] = 0ull;
        for (int t = 0; t < 49; t++) {
            float2 Pf = Ps[t * 64 + c];
            u64 px = pk1(Pf.x), py = pk1(Pf.y);
#pragma unroll
            for (int j = 0; j < 4; j++) {
                int kt = ktg * 4 + j;
                float4 e = ets4[kt * 49 + t];
                fma2(Q[j], px, *(u64*)&e.x);
                fma2(Q[j], py, *(u64*)&e.z);
            }
        }
#pragma unroll
        for (int j = 0; j < 4; j++)
            Qs[(ktg * 4 + j) * 64 + c] = up2(Q[j]);
    }
    __syncthreads();   // Ps dead, Qs visible
    for (int i = tid; i < 784; i += 256) {
        float2 c1 = g_ct1[i], c2 = g_ct2[i];
        cts4[i] = make_float4(c1.x, c1.y, c2.x, c2.y);
    }
    // phase2: mix, packed weights (1 LDG.128 per c)
    for (int i = tid; i < 1024; i += 256) {
        int kt = i >> 6, o = i & 63;
        u64 S = 0ull;
        size_t wb = ((size_t)(l * 256 + kx * 16 + kt)) * 4096 + o;
        for (int c = 0; c < 64; c++) {
            float2 q = Qs[kt * 64 + c];
            float4 w = g_wtp[wb + c * 64];
            fma2(S, pk1(q.x), *(u64*)&w.x);
            fma2(S, pk1(q.y), *(u64*)&w.z);
        }
        Ss[i] = up2(S);
    }
    __syncthreads();
    // phase3: inv t-DFT, kt outer, R in regs
    {
        int o = tid & 63, tg = tid >> 6;
        u64 R[13];
#pragma unroll
        for (int it = 0; it < 13; it++) R[it] = 0ull;
#pragma unroll 4
        for (int kt = 0; kt < 16; kt++) {
            float2 s = Ss[kt * 64 + o];
            u64 px = pk1(s.x), py = pk1(s.y);
#pragma unroll
            for (int it = 0; it < 13; it++) {
                int t = tg + it * 4;
                if (t < 49) {
                    float4 ct = cts4[kt * 49 + t];
                    fma2(R[it], px, *(u64*)&ct.x);
                    fma2(R[it], py, *(u64*)&ct.z);
                }
            }
        }
#pragma unroll
        for (int it = 0; it < 13; it++) {
            int t = tg + it * 4;
            if (t < 49) g_rc[base + t * 64 + o] = up2(R[it]);
        }
    }
}

// ---------- inverse x-DFT: 2 cols/thread, kx-half split (R13 proven) ----------
__global__ void __launch_bounds__(224) k_ix() {
    __shared__ float2 exs[8 * 176];
    int jt = blockIdx.x;            // 0..6
    int yz = blockIdx.y;            // 0..5 : xc = yz>>1, kxh = (yz&1)*8
    int b = blockIdx.z;
    int tid = threadIdx.x;
    int xc = yz >> 1, kxh = (yz & 1) * 8;
    int col0 = (jt * 224 + tid) * 2;
    int x0 = xc * 174;
    int cnt = min(174, XD - x0);
    ulonglong2 Rv[8];
#pragma unroll
    for (int kx = 0; kx < 8; kx++)
        Rv[kx] = *(const ulonglong2*)(&g_rc[((size_t)(b * 16 + kxh + kx)) * VROW + col0]);
    for (int i = tid; i < 8 * cnt; i += 224) {
        int kx = i / cnt, xl = i - kx * cnt;
        exs[kx * 176 + xl] = g_exE[(kxh + kx) * 521 + x0 + xl];
    }
    __syncthreads();
    float* dst = kxh ? g_u1b : g_u1;
    for (int xl = 0; xl < cnt; xl++) {
        u64 d0 = 0ull, d1 = 0ull;
#pragma unroll
        for (int kx = 0; kx < 8; kx++) {
            u64 E = *(const u64*)&exs[kx * 176 + xl];
            fma2(d0, Rv[kx].x, E);
            fma2(d1, Rv[kx].y, E);
        }
        float2 f0 = up2(d0), f1 = up2(d1);
        *(u64*)(dst + (size_t)(b * XD + x0 + xl) * VROW + col0) = pk(f0.x + f0.y, f1.x + f1.y);
    }
}

// ---------- conv (64x64) + bias + u1a+u1b + gelu, in-place ----------
__global__ void __launch_bounds__(128) k_conv(const float* __restrict__ wconv,
                                              const float* __restrict__ wbias,
                                              int l, int last) {
    __shared__ __align__(16) float v_sh[3328];
    __shared__ __align__(16) float wT[4096];
    __shared__ __align__(16) float bsh[64];
    int x = blockIdx.x, b = blockIdx.y, tid = threadIdx.x;
    size_t vb = ((size_t)(b * XD + x)) * VROW;
    for (int i = tid; i < 784; i += 128) ((float4*)v_sh)[i] = ((const float4*)(g_v + vb))[i];
    for (int i = 3136 + tid; i < 3328; i += 128) v_sh[i] = 0.f;
    for (int i = tid; i < 4096; i += 128) {
        int o = i >> 6, c = i & 63;
        wT[c * 64 + o] = wconv[l * 4096 + i];
    }
    if (tid < 64) bsh[tid] = wbias[l * 64 + tid];
    __syncthreads();

    int og = tid & 7, tg = tid >> 3;
    int t0 = tg * 4;
    if (t0 >= 49) return;
    u64 A[4][4];
    {
        const ulonglong2* bp = (const ulonglong2*)bsh;
        ulonglong2 B0 = bp[og * 2], B1 = bp[og * 2 + 1];
#pragma unroll
        for (int tt = 0; tt < 4; tt++) {
            A[tt][0] = B0.x; A[tt][1] = B0.y; A[tt][2] = B1.x; A[tt][3] = B1.y;
        }
    }
    const float4* v4p = (const float4*)v_sh;
    const ulonglong2* wp2 = (const ulonglong2*)wT;
#pragma unroll 4
    for (int cq = 0; cq < 16; cq++) {
        float4 v0 = v4p[(t0 + 0) * 16 + cq];
        float4 v1 = v4p[(t0 + 1) * 16 + cq];
        float4 v2 = v4p[(t0 + 2) * 16 + cq];
        float4 v3 = v4p[(t0 + 3) * 16 + cq];
#pragma unroll
        for (int cc = 0; cc < 4; cc++) {
            int c = cq * 4 + cc;
            ulonglong2 W0 = wp2[c * 16 + og * 2];
            ulonglong2 W1 = wp2[c * 16 + og * 2 + 1];
            float s0 = (cc == 0) ? v0.x : (cc == 1) ? v0.y : (cc == 2) ? v0.z : v0.w;
            float s1 = (cc == 0) ? v1.x : (cc == 1) ? v1.y : (cc == 2) ? v1.z : v1.w;
            float s2 = (cc == 0) ? v2.x : (cc == 1) ? v2.y : (cc == 2) ? v2.z : v2.w;
            float s3 = (cc == 0) ? v3.x : (cc == 1) ? v3.y : (cc == 2) ? v3.z : v3.w;
            u64 p0 = pk1(s0), p1 = pk1(s1), p2 = pk1(s2), p3 = pk1(s3);
            fma2(A[0][0], W0.x, p0); fma2(A[0][1], W0.y, p0); fma2(A[0][2], W1.x, p0); fma2(A[0][3], W1.y, p0);
            fma2(A[1][0], W0.x, p1); fma2(A[1][1], W0.y, p1); fma2(A[1][2], W1.x, p1); fma2(A[1][3], W1.y, p1);
            fma2(A[2][0], W0.x, p2); fma2(A[2][1], W0.y, p2); fma2(A[2][2], W1.x, p2); fma2(A[2][3], W1.y, p2);
            fma2(A[3][0], W0.x, p3); fma2(A[3][1], W0.y, p3); fma2(A[3][2], W1.x, p3); fma2(A[3][3], W1.y, p3);
        }
    }
#pragma unroll
    for (int tt = 0; tt < 4; tt++) {
        int t = t0 + tt;
        if (t < 49) {
            size_t bu = vb + t * 64 + og * 8;
            ulonglong2 U0 = *(const ulonglong2*)(g_u1 + bu);
            ulonglong2 U1 = *(const ulonglong2*)(g_u1 + bu + 4);
            ulonglong2 V0 = *(const ulonglong2*)(g_u1b + bu);
            ulonglong2 V1 = *(const ulonglong2*)(g_u1b + bu + 4);
            add2(A[tt][0], U0.x); add2(A[tt][1], U0.y);
            add2(A[tt][2], U1.x); add2(A[tt][3], U1.y);
            add2(A[tt][0], V0.x); add2(A[tt][1], V0.y);
            add2(A[tt][2], V1.x); add2(A[tt][3], V1.y);
            float2 r0 = up2(A[tt][0]), r1 = up2(A[tt][1]);
            float2 r2 = up2(A[tt][2]), r3 = up2(A[tt][3]);
            float4 fa, fb;
            if (!last) {
                fa = make_float4(gelu_f(r0.x), gelu_f(r0.y), gelu_f(r1.x), gelu_f(r1.y));
                fb = make_float4(gelu_f(r2.x), gelu_f(r2.y), gelu_f(r3.x), gelu_f(r3.y));
            } else {
                fa = make_float4(r0.x, r0.y, r1.x, r1.y);
                fb = make_float4(r2.x, r2.y, r3.x, r3.y);
            }
            ((float4*)(g_v + vb))[t * 16 + og * 2] = fa;
            ((float4*)(g_v + vb))[t * 16 + og * 2 + 1] = fb;
        }
    }
}

// ---------- crop + fc1 + gelu + fc2 ----------
__global__ void __launch_bounds__(256) k_final(const float* __restrict__ w1,
                                               const float* __restrict__ b1,
                                               const float* __restrict__ w2,
                                               const float* __restrict__ b2,
                                               float* __restrict__ out) {
    __shared__ __align__(16) float w1s[64 * 128];
    __shared__ __align__(16) float vs[40 * 64];
    __shared__ __align__(16) float b1s[128], w2s[128];
    __shared__ float b2s;
    int x = blockIdx.x, b = blockIdx.y, tid = threadIdx.x;
    for (int i = tid; i < 2048; i += 256)
        ((float4*)w1s)[i] = ((const float4*)w1)[i];
    if (tid < 128) { b1s[tid] = b1[tid]; w2s[tid] = w2[tid]; }
    if (tid == 0) b2s = b2[0];
    size_t vb = ((size_t)(b * XD + x)) * VROW;
    for (int i = tid; i < 640; i += 256) ((float4*)vs)[i] = ((const float4*)(g_v + vb))[i];
    __syncthreads();
    int lane = tid & 31, wp = tid >> 5;
    u64 H[5][2];
    ulonglong2 bq = ((const ulonglong2*)b1s)[lane];
#pragma unroll
    for (int s = 0; s < 5; s++) { H[s][0] = bq.x; H[s][1] = bq.y; }
    const ulonglong2* w1p = (const ulonglong2*)w1s;
#pragma unroll 4
    for (int c = 0; c < 64; c++) {
        ulonglong2 w2v = w1p[c * 32 + lane];
#pragma unroll
        for (int s = 0; s < 5; s++) {
            u64 vv = pk1(vs[(wp + 8 * s) * 64 + c]);
            fma2(H[s][0], w2v.x, vv);
            fma2(H[s][1], w2v.y, vv);
        }
    }
    float4 w2q = ((const float4*)w2s)[lane];
#pragma unroll
    for (int s = 0; s < 5; s++) {
        float2 hlo = up2(H[s][0]), hhi = up2(H[s][1]);
        float acc = gelu_f(hlo.x) * w2q.x + gelu_f(hlo.y) * w2q.y +
                    gelu_f(hhi.x) * w2q.z + gelu_f(hhi.y) * w2q.w;
#pragma unroll
        for (int off = 16; off; off >>= 1) acc += __shfl_xor_sync(0xffffffffu, acc, off);
        if (lane == 0) out[((size_t)(b * 512 + x)) * 40 + wp + 8 * s] = acc + b2s;
    }
}

extern "C" void kernel_launch(void* const* d_in, const int* in_sizes, int n_in,
                              void* d_out, int out_size) {
    (void)in_sizes; (void)n_in; (void)out_size;
    const float* u      = (const float*)d_in[0];
    const float* xin    = (const float*)d_in[1];
    const float* tin    = (const float*)d_in[2];
    const float* par    = (const float*)d_in[3];
    const float* fc0_w  = (const float*)d_in[4];
    const float* fc0_b  = (const float*)d_in[5];
    const float* spec_wr = (const float*)d_in[6];
    const float* spec_wi = (const float*)d_in[7];
    const float* w_conv = (const float*)d_in[8];
    const float* w_bias = (const float*)d_in[9];
    const float* fc1_w  = (const float*)d_in[10];
    const float* fc1_b  = (const float*)d_in[11];
    const float* fc2_w  = (const float*)d_in[12];
    const float* fc2_b  = (const float*)d_in[13];
    float* out = (float*)d_out;

    k_tables<<<33, 256>>>();
    k_wt2<<<dim3(4, 64, 4), 256>>>(spec_wr, spec_wi);
    k_embed<<<dim3(131, NB), 256>>>(u, xin, tin, par, fc0_w, fc0_b);
    for (int l = 0; l < 4; l++) {
        k_fx<<<dim3(7, 4, NB), 224>>>();
        k_spec<<<dim3(16, NB), 256>>>(l);
        k_ix<<<dim3(7, 6, NB), 224>>>();
        k_conv<<<dim3(XD, NB), 128>>>(w_conv, w_bias, l, l == 3 ? 1 : 0);
    }
    k_final<<<dim3(512, NB), 256>>>(fc1_w, fc1_b, fc2_w, fc2_b, out);
}

// round 16
// speedup vs baseline: 1.0659x; 1.0027x over previous
#include <cuda_runtime.h>
#include <math.h>

#define NB 32
#define XD 521
#define TD 49
#define CW 64
#define VROW 3136                 // TD*CW
#define V_ELEMS  52283392ull      // NB*XD*VROW
#define PC_ELEMS 1605632ull      // NB*16*VROW (float2)
#define WT_ELEMS 4194304ull      // 4*256*64*64

typedef unsigned long long u64;

__device__ float g_v[V_ELEMS];
__device__ float g_u1[V_ELEMS];
__device__ float g_u1b[V_ELEMS];
__device__ float2 g_pc[PC_ELEMS];     // P partial (x-half 0)
__device__ float2 g_pc2[PC_ELEMS];    // P partial (x-half 1)
__device__ float2 g_rc[PC_ELEMS];     // R[b][kx][t*64+o]
__device__ float4 g_wtp[WT_ELEMS];    // (wr, wi, -wi, wr)  [l][m][c][o]
__device__ float2 g_exE[16 * 521];    // fwd x twiddle
__device__ float2 g_et1[784];         // [kt][t] fwd t
__device__ float2 g_et2[784];
__device__ float2 g_ct1[784];         // inv t (scaled)
__device__ float2 g_ct2[784];

__device__ __forceinline__ float gelu_f(float v) {
    return 0.5f * v * (1.0f + erff(v * 0.70710678118654752f));
}
__device__ __forceinline__ u64 pk(float lo, float hi) {
    u64 r; asm("mov.b64 %0,{%1,%2};" : "=l"(r) : "f"(lo), "f"(hi)); return r;
}
__device__ __forceinline__ u64 pk1(float v) { return pk(v, v); }
__device__ __forceinline__ void fma2(u64& d, u64 a, u64 b) {
    asm("fma.rn.f32x2 %0,%1,%2,%0;" : "+l"(d) : "l"(a), "l"(b));
}
__device__ __forceinline__ void add2(u64& d, u64 a) {
    asm("add.rn.f32x2 %0,%0,%1;" : "+l"(d) : "l"(a));
}
__device__ __forceinline__ float2 up2(u64 v) {
    float2 r; asm("mov.b64 {%0,%1},%2;" : "=f"(r.x), "=f"(r.y) : "l"(v)); return r;
}

// ---------- tables ----------
__global__ void k_tables() {
    int idx = blockIdx.x * blockDim.x + threadIdx.x;
    const double PI2 = 6.283185307179586476925287;
    if (idx < 784) {
        int kt = idx / 49, t = idx % 49;
        double a = -PI2 * (double)((kt * t) % 49) / 49.0;
        float er = (float)cos(a), ei = (float)sin(a);
        g_et1[idx] = make_float2(er, ei);
        g_et2[idx] = make_float2(-ei, er);
        float w = (kt == 0 ? 1.0f : 2.0f) * (float)(1.0 / (521.0 * 49.0));
        float ct = w * er;
        float cs = w * (-ei);
        g_ct1[idx] = make_float2(ct, cs);
        g_ct2[idx] = make_float2(-cs, ct);
    }
    if (idx < 8336) {
        int kx = idx / 521, x = idx % 521;
        double a = -PI2 * (double)((kx * x) % 521) / 521.0;
        g_exE[idx] = make_float2((float)cos(a), (float)sin(a));
    }
}

// ---------- spectral weight pack: (wr,wi,-wi,wr) float4 ----------
__global__ void k_wt2(const float* __restrict__ wr, const float* __restrict__ wi) {
    __shared__ float shr[64 * 65], shi[64 * 65];
    int mc = blockIdx.x, i = blockIdx.y, l = blockIdx.z, tid = threadIdx.x;
    size_t srcbase = ((size_t)(l * 64 + i)) * 64 * 256 + (size_t)mc * 64;
    for (int idx = tid; idx < 4096; idx += 256) {
        int o = idx >> 6, mm = idx & 63;
        shr[o * 65 + mm] = wr[srcbase + (size_t)o * 256 + mm];
        shi[o * 65 + mm] = wi[srcbase + (size_t)o * 256 + mm];
    }
    __syncthreads();
    for (int idx = tid; idx < 4096; idx += 256) {
        int mm = idx >> 6, o = idx & 63;
        int m = mc * 64 + mm;
        float r = shr[o * 65 + mm], im = shi[o * 65 + mm];
        size_t d = (((size_t)(l * 256 + m)) * 64 + i) * 64 + o;
        g_wtp[d] = make_float4(r, im, -im, r);
    }
}

// ---------- embed ----------
__global__ void __launch_bounds__(256) k_embed(const float* __restrict__ u,
                                               const float* __restrict__ xin,
                                               const float* __restrict__ tin,
                                               const float* __restrict__ par,
                                               const float* __restrict__ w0,
                                               const float* __restrict__ b0) {
    __shared__ float feat[4][16];
    __shared__ float tv[40];
    int xq = blockIdx.x, b = blockIdx.y, tid = threadIdx.x;
    int xh = tid >> 6, c = tid & 63;
    int x = xq * 4 + xh;
    if (tid < 40) tv[tid] = tin[b * 40 + tid];
    if (c < 13 && x < 512) {
        float f;
        if (c < 10) f = u[((size_t)(b * 512 + x)) * 10 + c];
        else if (c < 12) f = par[b * 2 + c - 10];
        else f = xin[b * 512 + x];
        feat[xh][c] = f;
    }
    __syncthreads();
    if (x >= XD) return;
    bool vx = (x < 512);
    size_t vb = ((size_t)(b * XD + x)) * VROW;
    float basev = 0.f, w13c = 0.f;
    if (vx) {
        basev = b0[c];
#pragma unroll
        for (int k = 0; k < 13; k++) basev += feat[xh][k] * w0[k * 64 + c];
        w13c = w0[13 * 64 + c];
    }
    for (int t = 0; t < 40; t++)
        g_v[vb + t * 64 + c] = vx ? fmaf(tv[t], w13c, basev) : 0.f;
    for (int t = 40; t < 49; t++) g_v[vb + t * 64 + c] = 0.f;
}

// ---------- forward x-DFT: 2 cols/thread, 8 kx, 2 x-halves ----------
__global__ void __launch_bounds__(224, 4) k_fx() {
    __shared__ float2 exs[8 * 132];
    int jt = blockIdx.x;            // 0..6 col tile
    int q = blockIdx.y;             // 0..3 : kxh = q&1, xhf = q>>1
    int b = blockIdx.z;
    int tid = threadIdx.x;
    int kxh = (q & 1) * 8, xhf = q >> 1;
    int col0 = (jt * 224 + tid) * 2;
    int xbeg = xhf * 261, xend = xhf ? 521 : 261;
    size_t vb = (size_t)b * XD * VROW;
    u64 a0[8], a1[8];
#pragma unroll
    for (int kx = 0; kx < 8; kx++) { a0[kx] = 0ull; a1[kx] = 0ull; }
    for (int ch = 0; ch < 2; ch++) {
        int x0 = xbeg + ch * 131;
        int cnt = min(131, xend - x0);
        __syncthreads();
        for (int i = tid; i < 8 * cnt; i += 224) {
            int kx = i / cnt, xl = i - kx * cnt;
            exs[kx * 132 + xl] = g_exE[(kxh + kx) * 521 + x0 + xl];
        }
        __syncthreads();
        for (int xl = 0; xl < cnt; xl++) {
            u64 v2 = *(const u64*)(g_v + vb + (size_t)(x0 + xl) * VROW + col0);
            float2 vv = up2(v2);
            u64 va = pk1(vv.x), vc = pk1(vv.y);
#pragma unroll
            for (int kx = 0; kx < 8; kx++) {
                u64 E = *(const u64*)&exs[kx * 132 + xl];
                fma2(a0[kx], va, E);
                fma2(a1[kx], vc, E);
            }
        }
    }
    float2* dst = xhf ? g_pc2 : g_pc;
#pragma unroll
    for (int kx = 0; kx < 8; kx++) {
        ulonglong2 st;
        st.x = a0[kx]; st.y = a1[kx];
        *(ulonglong2*)(&dst[((size_t)(b * 16 + kxh + kx)) * VROW + col0]) = st;
    }
}

// ---------- spectral: t-DFT + channel mix + inv t-DFT per (kx, b), smem twiddles ----------
__global__ void __launch_bounds__(256) k_spec(int l) {
    // region A: [0, 25088)  Ps -> after phase1: cts4 (12544) @0, Ss (8192) @12544
    // region B: [25088, 37632) ets4
    // region C: [37632, 45824) Qs
    __shared__ __align__(16) char sm[45824];
    float2* Ps   = (float2*)sm;
    float4* ets4 = (float4*)(sm + 25088);
    float2* Qs   = (float2*)(sm + 37632);
    float4* cts4 = (float4*)sm;
    float2* Ss   = (float2*)(sm + 12544);
    int kx = blockIdx.x, b = blockIdx.y, tid = threadIdx.x;
    size_t base = ((size_t)(b * 16 + kx)) * VROW;
    for (int i = tid; i < VROW; i += 256) {
        float2 p0 = g_pc[base + i], p1 = g_pc2[base + i];
        Ps[i] = make_float2(p0.x + p1.x, p0.y + p1.y);
    }
    for (int i = tid; i < 784; i += 256) {
        float2 e1 = g_et1[i], e2 = g_et2[i];
        ets4[i] = make_float4(e1.x, e1.y, e2.x, e2.y);
    }
    __syncthreads();
    // phase1: t-DFT. thread owns (c, 4 kt)
    {
        int c = tid & 63, ktg = tid >> 6;
        u64 Q[4];
#pragma unroll
        for (int j = 0; j < 4; j++) Q[j] = 0ull;
        for (int t = 0; t < 49; t++) {
            float2 Pf = Ps[t * 64 + c];
            u64 px = pk1(Pf.x), py = pk1(Pf.y);
#pragma unroll
            for (int j = 0; j < 4; j++) {
                int kt = ktg * 4 + j;
                float4 e = ets4[kt * 49 + t];
                fma2(Q[j], px, *(u64*)&e.x);
                fma2(Q[j], py, *(u64*)&e.z);
            }
        }
#pragma unroll
        for (int j = 0; j < 4; j++)
            Qs[(ktg * 4 + j) * 64 + c] = up2(Q[j]);
    }
    __syncthreads();   // Ps dead, Qs visible
    for (int i = tid; i < 784; i += 256) {
        float2 c1 = g_ct1[i], c2 = g_ct2[i];
        cts4[i] = make_float4(c1.x, c1.y, c2.x, c2.y);
    }
    // phase2: mix, packed weights (1 LDG.128 per c)
    for (int i = tid; i < 1024; i += 256) {
        int kt = i >> 6, o = i & 63;
        u64 S = 0ull;
        size_t wb = ((size_t)(l * 256 + kx * 16 + kt)) * 4096 + o;
        for (int c = 0; c < 64; c++) {
            float2 q = Qs[kt * 64 + c];
            float4 w = g_wtp[wb + c * 64];
            fma2(S, pk1(q.x), *(u64*)&w.x);
            fma2(S, pk1(q.y), *(u64*)&w.z);
        }
        Ss[i] = up2(S);
    }
    __syncthreads();
    // phase3: inv t-DFT, kt outer, R in regs
    {
        int o = tid & 63, tg = tid >> 6;
        u64 R[13];
#pragma unroll
        for (int it = 0; it < 13; it++) R[it] = 0ull;
#pragma unroll 4
        for (int kt = 0; kt < 16; kt++) {
            float2 s = Ss[kt * 64 + o];
            u64 px = pk1(s.x), py = pk1(s.y);
#pragma unroll
            for (int it = 0; it < 13; it++) {
                int t = tg + it * 4;
                if (t < 49) {
                    float4 ct = cts4[kt * 49 + t];
                    fma2(R[it], px, *(u64*)&ct.x);
                    fma2(R[it], py, *(u64*)&ct.z);
                }
            }
        }
#pragma unroll
        for (int it = 0; it < 13; it++) {
            int t = tg + it * 4;
            if (t < 49) g_rc[base + t * 64 + o] = up2(R[it]);
        }
    }
}

// ---------- inverse x-DFT: 2 cols/thread, kx-half split ----------
__global__ void __launch_bounds__(224, 4) k_ix() {
    __shared__ float2 exs[8 * 176];
    int jt = blockIdx.x;            // 0..6
    int yz = blockIdx.y;            // 0..5 : xc = yz>>1, kxh = (yz&1)*8
    int b = blockIdx.z;
    int tid = threadIdx.x;
    int xc = yz >> 1, kxh = (yz & 1) * 8;
    int col0 = (jt * 224 + tid) * 2;
    int x0 = xc * 174;
    int cnt = min(174, XD - x0);
    ulonglong2 Rv[8];
#pragma unroll
    for (int kx = 0; kx < 8; kx++)
        Rv[kx] = *(const ulonglong2*)(&g_rc[((size_t)(b * 16 + kxh + kx)) * VROW + col0]);
    for (int i = tid; i < 8 * cnt; i += 224) {
        int kx = i / cnt, xl = i - kx * cnt;
        exs[kx * 176 + xl] = g_exE[(kxh + kx) * 521 + x0 + xl];
    }
    __syncthreads();
    float* dst = kxh ? g_u1b : g_u1;
    for (int xl = 0; xl < cnt; xl++) {
        u64 d0 = 0ull, d1 = 0ull;
#pragma unroll
        for (int kx = 0; kx < 8; kx++) {
            u64 E = *(const u64*)&exs[kx * 176 + xl];
            fma2(d0, Rv[kx].x, E);
            fma2(d1, Rv[kx].y, E);
        }
        float2 f0 = up2(d0), f1 = up2(d1);
        *(u64*)(dst + (size_t)(b * XD + x0 + xl) * VROW + col0) = pk(f0.x + f0.y, f1.x + f1.y);
    }
}

// ---------- conv (64x64) + bias + u1a+u1b + gelu, in-place ----------
__global__ void __launch_bounds__(128) k_conv(const float* __restrict__ wconv,
                                              const float* __restrict__ wbias,
                                              int l, int last) {
    __shared__ __align__(16) float v_sh[3328];
    __shared__ __align__(16) float wT[4096];
    __shared__ __align__(16) float bsh[64];
    int x = blockIdx.x, b = blockIdx.y, tid = threadIdx.x;
    size_t vb = ((size_t)(b * XD + x)) * VROW;
    for (int i = tid; i < 784; i += 128) ((float4*)v_sh)[i] = ((const float4*)(g_v + vb))[i];
    for (int i = 3136 + tid; i < 3328; i += 128) v_sh[i] = 0.f;
    for (int i = tid; i < 4096; i += 128) {
        int o = i >> 6, c = i & 63;
        wT[c * 64 + o] = wconv[l * 4096 + i];
    }
    if (tid < 64) bsh[tid] = wbias[l * 64 + tid];
    __syncthreads();

    int og = tid & 7, tg = tid >> 3;
    int t0 = tg * 4;
    if (t0 >= 49) return;
    u64 A[4][4];
    {
        const ulonglong2* bp = (const ulonglong2*)bsh;
        ulonglong2 B0 = bp[og * 2], B1 = bp[og * 2 + 1];
#pragma unroll
        for (int tt = 0; tt < 4; tt++) {
            A[tt][0] = B0.x; A[tt][1] = B0.y; A[tt][2] = B1.x; A[tt][3] = B1.y;
        }
    }
    const float4* v4p = (const float4*)v_sh;
    const ulonglong2* wp2 = (const ulonglong2*)wT;
#pragma unroll 4
    for (int cq = 0; cq < 16; cq++) {
        float4 v0 = v4p[(t0 + 0) * 16 + cq];
        float4 v1 = v4p[(t0 + 1) * 16 + cq];
        float4 v2 = v4p[(t0 + 2) * 16 + cq];
        float4 v3 = v4p[(t0 + 3) * 16 + cq];
#pragma unroll
        for (int cc = 0; cc < 4; cc++) {
            int c = cq * 4 + cc;
            ulonglong2 W0 = wp2[c * 16 + og * 2];
            ulonglong2 W1 = wp2[c * 16 + og * 2 + 1];
            float s0 = (cc == 0) ? v0.x : (cc == 1) ? v0.y : (cc == 2) ? v0.z : v0.w;
            float s1 = (cc == 0) ? v1.x : (cc == 1) ? v1.y : (cc == 2) ? v1.z : v1.w;
            float s2 = (cc == 0) ? v2.x : (cc == 1) ? v2.y : (cc == 2) ? v2.z : v2.w;
            float s3 = (cc == 0) ? v3.x : (cc == 1) ? v3.y : (cc == 2) ? v3.z : v3.w;
            u64 p0 = pk1(s0), p1 = pk1(s1), p2 = pk1(s2), p3 = pk1(s3);
            fma2(A[0][0], W0.x, p0); fma2(A[0][1], W0.y, p0); fma2(A[0][2], W1.x, p0); fma2(A[0][3], W1.y, p0);
            fma2(A[1][0], W0.x, p1); fma2(A[1][1], W0.y, p1); fma2(A[1][2], W1.x, p1); fma2(A[1][3], W1.y, p1);
            fma2(A[2][0], W0.x, p2); fma2(A[2][1], W0.y, p2); fma2(A[2][2], W1.x, p2); fma2(A[2][3], W1.y, p2);
            fma2(A[3][0], W0.x, p3); fma2(A[3][1], W0.y, p3); fma2(A[3][2], W1.x, p3); fma2(A[3][3], W1.y, p3);
        }
    }
#pragma unroll
    for (int tt = 0; tt < 4; tt++) {
        int t = t0 + tt;
        if (t < 49) {
            size_t bu = vb + t * 64 + og * 8;
            ulonglong2 U0 = *(const ulonglong2*)(g_u1 + bu);
            ulonglong2 U1 = *(const ulonglong2*)(g_u1 + bu + 4);
            ulonglong2 V0 = *(const ulonglong2*)(g_u1b + bu);
            ulonglong2 V1 = *(const ulonglong2*)(g_u1b + bu + 4);
            add2(A[tt][0], U0.x); add2(A[tt][1], U0.y);
            add2(A[tt][2], U1.x); add2(A[tt][3], U1.y);
            add2(A[tt][0], V0.x); add2(A[tt][1], V0.y);
            add2(A[tt][2], V1.x); add2(A[tt][3], V1.y);
            float2 r0 = up2(A[tt][0]), r1 = up2(A[tt][1]);
            float2 r2 = up2(A[tt][2]), r3 = up2(A[tt][3]);
            float4 fa, fb;
            if (!last) {
                fa = make_float4(gelu_f(r0.x), gelu_f(r0.y), gelu_f(r1.x), gelu_f(r1.y));
                fb = make_float4(gelu_f(r2.x), gelu_f(r2.y), gelu_f(r3.x), gelu_f(r3.y));
            } else {
                fa = make_float4(r0.x, r0.y, r1.x, r1.y);
                fb = make_float4(r2.x, r2.y, r3.x, r3.y);
            }
            ((float4*)(g_v + vb))[t * 16 + og * 2] = fa;
            ((float4*)(g_v + vb))[t * 16 + og * 2 + 1] = fb;
        }
    }
}

// ---------- crop + fc1 + gelu + fc2 : 2 x per block ----------
__global__ void __launch_bounds__(256) k_final(const float* __restrict__ w1,
                                               const float* __restrict__ b1,
                                               const float* __restrict__ w2,
                                               const float* __restrict__ b2,
                                               float* __restrict__ out) {
    __shared__ __align__(16) float w1s[64 * 128];
    __shared__ __align__(16) float vs[2][40 * 64];
    __shared__ __align__(16) float b1s[128], w2s[128];
    __shared__ float b2s;
    int xp = blockIdx.x, b = blockIdx.y, tid = threadIdx.x;
    for (int i = tid; i < 2048; i += 256)
        ((float4*)w1s)[i] = ((const float4*)w1)[i];
    if (tid < 128) { b1s[tid] = b1[tid]; w2s[tid] = w2[tid]; }
    if (tid == 0) b2s = b2[0];
    size_t vb0 = ((size_t)(b * XD + xp * 2)) * VROW;
    size_t vb1 = vb0 + VROW;
    for (int i = tid; i < 640; i += 256) {
        ((float4*)vs[0])[i] = ((const float4*)(g_v + vb0))[i];
        ((float4*)vs[1])[i] = ((const float4*)(g_v + vb1))[i];
    }
    __syncthreads();
    int lane = tid & 31, wp = tid >> 5;
    const ulonglong2* w1p = (const ulonglong2*)w1s;
    ulonglong2 bq = ((const ulonglong2*)b1s)[lane];
    float4 w2q = ((const float4*)w2s)[lane];
#pragma unroll
    for (int h = 0; h < 2; h++) {
        int x = xp * 2 + h;
        u64 H[5][2];
#pragma unroll
        for (int s = 0; s < 5; s++) { H[s][0] = bq.x; H[s][1] = bq.y; }
#pragma unroll 4
        for (int c = 0; c < 64; c++) {
            ulonglong2 w2v = w1p[c * 32 + lane];
#pragma unroll
            for (int s = 0; s < 5; s++) {
                u64 vv = pk1(vs[h][(wp + 8 * s) * 64 + c]);
                fma2(H[s][0], w2v.x, vv);
                fma2(H[s][1], w2v.y, vv);
            }
        }
#pragma unroll
        for (int s = 0; s < 5; s++) {
            float2 hlo = up2(H[s][0]), hhi = up2(H[s][1]);
            float acc = gelu_f(hlo.x) * w2q.x + gelu_f(hlo.y) * w2q.y +
                        gelu_f(hhi.x) * w2q.z + gelu_f(hhi.y) * w2q.w;
#pragma unroll
            for (int off = 16; off; off >>= 1) acc += __shfl_xor_sync(0xffffffffu, acc, off);
            if (lane == 0) out[((size_t)(b * 512 + x)) * 40 + wp + 8 * s] = acc + b2s;
        }
    }
}

extern "C" void kernel_launch(void* const* d_in, const int* in_sizes, int n_in,
                              void* d_out, int out_size) {
    (void)in_sizes; (void)n_in; (void)out_size;
    const float* u      = (const float*)d_in[0];
    const float* xin    = (const float*)d_in[1];
    const float* tin    = (const float*)d_in[2];
    const float* par    = (const float*)d_in[3];
    const float* fc0_w  = (const float*)d_in[4];
    const float* fc0_b  = (const float*)d_in[5];
    const float* spec_wr = (const float*)d_in[6];
    const float* spec_wi = (const float*)d_in[7];
    const float* w_conv = (const float*)d_in[8];
    const float* w_bias = (const float*)d_in[9];
    const float* fc1_w  = (const float*)d_in[10];
    const float* fc1_b  = (const float*)d_in[11];
    const float* fc2_w  = (const float*)d_in[12];
    const float* fc2_b  = (const float*)d_in[13];
    float* out = (float*)d_out;

    k_tables<<<33, 256>>>();
    k_wt2<<<dim3(4, 64, 4), 256>>>(spec_wr, spec_wi);
    k_embed<<<dim3(131, NB), 256>>>(u, xin, tin, par, fc0_w, fc0_b);
    for (int l = 0; l < 4; l++) {
        k_fx<<<dim3(7, 4, NB), 224>>>();
        k_spec<<<dim3(16, NB), 256>>>(l);
        k_ix<<<dim3(7, 6, NB), 224>>>();
        k_conv<<<dim3(XD, NB), 128>>>(w_conv, w_bias, l, l == 3 ? 1 : 0);
    }
    k_final<<<dim3(256, NB), 256>>>(fc1_w, fc1_b, fc2_w, fc2_b, out);
}